// round 1
// baseline (speedup 1.0000x reference)
#include <cuda_runtime.h>
#include <cstdint>

#define NTOK 65536
#define DM   256
#define NE   8
#define MT   64          // token tile (M)
#define KB   32          // K chunk
#define XS_STRIDE 260    // 256 + 4 pad -> conflict-free A-fragment loads
#define WS_STRIDE 264    // 256 + 8 pad -> conflict-free B-fragment loads
#define GEMM_THREADS 256
#define TILES_PER_E (NTOK / MT)   // 1024 worst case

// ---------------- scratch (device globals; no allocation allowed) ----------
__device__ int   g_cnt[NE];
__device__ int   g_off[NE];
__device__ int   g_assign[NTOK];
__device__ int   g_ticket[NTOK];
__device__ float g_gate[NTOK];
__device__ int   g_perm[NTOK];

// ---------------- small helpers -------------------------------------------
__device__ __forceinline__ uint32_t f2tf32(float f) {
    uint32_t r;
    asm("cvt.rna.tf32.f32 %0, %1;" : "=r"(r) : "f"(f));
    return r;
}

__device__ __forceinline__ void mma_tf32(float c[4], const uint32_t a[4],
                                         uint32_t b0, uint32_t b1) {
    asm volatile(
        "mma.sync.aligned.m16n8k8.row.col.f32.tf32.tf32.f32 "
        "{%0,%1,%2,%3}, {%4,%5,%6,%7}, {%8,%9}, {%0,%1,%2,%3};\n"
        : "+f"(c[0]), "+f"(c[1]), "+f"(c[2]), "+f"(c[3])
        : "r"(a[0]), "r"(a[1]), "r"(a[2]), "r"(a[3]), "r"(b0), "r"(b1));
}

// ---------------- kernel 0: zero counters ---------------------------------
__global__ void zero_kernel() {
    if (threadIdx.x < NE) g_cnt[threadIdx.x] = 0;
}

// ---------------- kernel 1: routing (logits + softmax + argmax + tickets) --
__global__ void __launch_bounds__(256) routing_kernel(
    const float* __restrict__ x, const float* __restrict__ wg)
{
    __shared__ float wgS[NE * DM];
    for (int i = threadIdx.x; i < NE * DM; i += blockDim.x) wgS[i] = wg[i];
    __syncthreads();

    int lane = threadIdx.x & 31;
    int warp = threadIdx.x >> 5;
    int gw   = blockIdx.x * 8 + warp;      // 256 blocks * 8 warps = 2048 warps

    int   myAssign = 0;
    int   myTok    = gw * 32 + lane;
    float myGate   = 0.f;

    for (int it = 0; it < 32; it++) {
        int tok = gw * 32 + it;
        const float* xr = x + (size_t)tok * DM;
        float acc[NE];
        #pragma unroll
        for (int e = 0; e < NE; e++) acc[e] = 0.f;
        #pragma unroll
        for (int j = 0; j < 8; j++) {
            float xv = xr[lane + 32 * j];
            #pragma unroll
            for (int e = 0; e < NE; e++)
                acc[e] += xv * wgS[e * DM + lane + 32 * j];
        }
        #pragma unroll
        for (int off = 16; off; off >>= 1) {
            #pragma unroll
            for (int e = 0; e < NE; e++)
                acc[e] += __shfl_xor_sync(0xffffffffu, acc[e], off);
        }
        // every lane now has all 8 logits; compute softmax top-1 redundantly
        float mx = acc[0]; int a = 0;
        #pragma unroll
        for (int e = 1; e < NE; e++) if (acc[e] > mx) { mx = acc[e]; a = e; }
        float s = 0.f;
        #pragma unroll
        for (int e = 0; e < NE; e++) s += expf(acc[e] - mx);
        float gate = 1.0f / s;             // == max of softmax
        if (it == lane) { myAssign = a; myGate = gate; }
    }

    // warp-aggregated atomics for the counter
    unsigned grp = __match_any_sync(0xffffffffu, myAssign);
    int leader = __ffs(grp) - 1;
    int rank   = __popc(grp & ((1u << lane) - 1));
    int base = 0;
    if (lane == leader) base = atomicAdd(&g_cnt[myAssign], __popc(grp));
    base = __shfl_sync(0xffffffffu, base, leader);

    g_assign[myTok] = myAssign;
    g_ticket[myTok] = base + rank;
    g_gate[myTok]   = myGate;
}

// ---------------- kernel 2: tiny exclusive scan ---------------------------
__global__ void scan_kernel() {
    int s = 0;
    for (int e = 0; e < NE; e++) { g_off[e] = s; s += g_cnt[e]; }
}

// ---------------- kernel 3: build permutation -----------------------------
__global__ void perm_kernel() {
    int i = blockIdx.x * blockDim.x + threadIdx.x;
    g_perm[g_off[g_assign[i]] + g_ticket[i]] = i;
}

// ---------------- grouped GEMM pieces -------------------------------------
__device__ __forceinline__ void ldg_chunk(const float* __restrict__ Wg, int kb,
                                          int tid, float4 w[8]) {
    #pragma unroll
    for (int j = 0; j < 8; j++) {
        int i = tid + j * GEMM_THREADS;
        int r = i >> 6, c4 = i & 63;
        w[j] = *reinterpret_cast<const float4*>(Wg + (kb * KB + r) * DM + c4 * 4);
    }
}

__device__ __forceinline__ void sts_chunk(float* __restrict__ Wbuf, int tid,
                                          const float4 w[8]) {
    #pragma unroll
    for (int j = 0; j < 8; j++) {
        int i = tid + j * GEMM_THREADS;
        int r = i >> 6, c4 = i & 63;
        float* p = Wbuf + r * WS_STRIDE + c4 * 4;
        p[0] = __uint_as_float(f2tf32(w[j].x));
        p[1] = __uint_as_float(f2tf32(w[j].y));
        p[2] = __uint_as_float(f2tf32(w[j].z));
        p[3] = __uint_as_float(f2tf32(w[j].w));
    }
}

__device__ __forceinline__ void compute_chunk(
    const float* __restrict__ Xs, const float* __restrict__ Wb,
    float acc[2][8][4], int kbase, int wm, int wn, int g, int tg)
{
    #pragma unroll
    for (int k8 = 0; k8 < KB / 8; k8++) {
        int k = k8 * 8;
        uint32_t a[2][4];
        #pragma unroll
        for (int mi = 0; mi < 2; mi++) {
            const float* xr = Xs + (wm * 32 + mi * 16 + g) * XS_STRIDE + kbase + k + tg;
            a[mi][0] = __float_as_uint(xr[0]);
            a[mi][1] = __float_as_uint(xr[8 * XS_STRIDE]);
            a[mi][2] = __float_as_uint(xr[4]);
            a[mi][3] = __float_as_uint(xr[8 * XS_STRIDE + 4]);
        }
        #pragma unroll
        for (int ni = 0; ni < 8; ni++) {
            int bc = wn * 64 + ni * 8 + g;
            uint32_t b0 = __float_as_uint(Wb[(k + tg) * WS_STRIDE + bc]);
            uint32_t b1 = __float_as_uint(Wb[(k + tg + 4) * WS_STRIDE + bc]);
            mma_tf32(acc[0][ni], a[0], b0, b1);
            mma_tf32(acc[1][ni], a[1], b0, b1);
        }
    }
}

__device__ __forceinline__ void run_stage(
    const float* __restrict__ Wg, const float* __restrict__ Xs,
    float* __restrict__ Ws, float acc[2][8][4],
    int tid, int wm, int wn, int g, int tg)
{
    #pragma unroll
    for (int mi = 0; mi < 2; mi++)
        #pragma unroll
        for (int ni = 0; ni < 8; ni++)
            #pragma unroll
            for (int q = 0; q < 4; q++) acc[mi][ni][q] = 0.f;

    float4 w[8];
    ldg_chunk(Wg, 0, tid, w);
    sts_chunk(Ws, tid, w);
    __syncthreads();

    #pragma unroll
    for (int kb = 0; kb < DM / KB; kb++) {
        if (kb + 1 < DM / KB) ldg_chunk(Wg, kb + 1, tid, w);
        compute_chunk(Xs, Ws + (kb & 1) * (KB * WS_STRIDE), acc, kb * KB, wm, wn, g, tg);
        if (kb + 1 < DM / KB) {
            sts_chunk(Ws + ((kb + 1) & 1) * (KB * WS_STRIDE), tid, w);
            __syncthreads();
        }
    }
}

// ---------------- kernel 4: grouped GEMM (gather -> FFN -> scatter) -------
__global__ void __launch_bounds__(GEMM_THREADS, 1) moe_gemm_kernel(
    const float* __restrict__ x,
    const float* __restrict__ W1, const float* __restrict__ b1,
    const float* __restrict__ W2, const float* __restrict__ b2,
    float* __restrict__ out)
{
    int e = blockIdx.x / TILES_PER_E;
    int t = blockIdx.x % TILES_PER_E;
    int cnt = g_cnt[e];
    int m0 = t * MT;
    if (m0 >= cnt) return;
    int rows = min(MT, cnt - m0);
    int base = g_off[e] + m0;

    extern __shared__ float smem[];
    float* Xs    = smem;                         // MT * XS_STRIDE
    float* Ws    = Xs + MT * XS_STRIDE;          // 2 * KB * WS_STRIDE
    float* gateS = Ws + 2 * KB * WS_STRIDE;      // MT
    float* biasS = gateS + MT;                   // DM
    int*   tokS  = (int*)(biasS + DM);           // MT

    int tid  = threadIdx.x;
    int lane = tid & 31, warp = tid >> 5;
    int wm = warp & 1, wn = warp >> 1;           // 2x4 warp grid
    int g = lane >> 2, tg = lane & 3;

    for (int i = tid; i < MT; i += GEMM_THREADS) {
        int tok = -1; float gt = 0.f;
        if (i < rows) { tok = g_perm[base + i]; gt = g_gate[tok]; }
        tokS[i] = tok; gateS[i] = gt;
    }
    for (int i = tid; i < DM; i += GEMM_THREADS) biasS[i] = b1[e * DM + i];
    __syncthreads();

    // gather X tile (zero-pad invalid rows), convert to tf32
    #pragma unroll
    for (int j = 0; j < MT * 64 / GEMM_THREADS; j++) {
        int i = tid + j * GEMM_THREADS;
        int r = i >> 6, c4 = i & 63;
        float4 v = make_float4(0.f, 0.f, 0.f, 0.f);
        int tok = tokS[r];
        if (tok >= 0)
            v = *reinterpret_cast<const float4*>(x + (size_t)tok * DM + c4 * 4);
        float* p = Xs + r * XS_STRIDE + c4 * 4;
        p[0] = __uint_as_float(f2tf32(v.x));
        p[1] = __uint_as_float(f2tf32(v.y));
        p[2] = __uint_as_float(f2tf32(v.z));
        p[3] = __uint_as_float(f2tf32(v.w));
    }
    __syncthreads();

    float acc[2][8][4];
    const float* W1e = W1 + (size_t)e * DM * DM;
    run_stage(W1e, Xs, Ws, acc, tid, wm, wn, g, tg);

    __syncthreads();   // everyone done reading Xs (and Ws) for GEMM1

    // epilogue 1: relu(acc + b1) -> Xs (as tf32)
    #pragma unroll
    for (int mi = 0; mi < 2; mi++) {
        #pragma unroll
        for (int ni = 0; ni < 8; ni++) {
            int col = wn * 64 + ni * 8 + tg * 2;
            int r0  = wm * 32 + mi * 16 + g;
            float bq0 = biasS[col], bq1 = biasS[col + 1];
            float v00 = fmaxf(acc[mi][ni][0] + bq0, 0.f);
            float v01 = fmaxf(acc[mi][ni][1] + bq1, 0.f);
            float v10 = fmaxf(acc[mi][ni][2] + bq0, 0.f);
            float v11 = fmaxf(acc[mi][ni][3] + bq1, 0.f);
            Xs[r0 * XS_STRIDE + col]           = __uint_as_float(f2tf32(v00));
            Xs[r0 * XS_STRIDE + col + 1]       = __uint_as_float(f2tf32(v01));
            Xs[(r0 + 8) * XS_STRIDE + col]     = __uint_as_float(f2tf32(v10));
            Xs[(r0 + 8) * XS_STRIDE + col + 1] = __uint_as_float(f2tf32(v11));
        }
    }
    __syncthreads();
    for (int i = tid; i < DM; i += GEMM_THREADS) biasS[i] = b2[e * DM + i];
    // biasS not read again until after run_stage (which contains syncthreads)

    const float* W2e = W2 + (size_t)e * DM * DM;
    run_stage(W2e, Xs, Ws, acc, tid, wm, wn, g, tg);

    // epilogue 2: (acc + b2) * gate -> scatter to out rows
    #pragma unroll
    for (int mi = 0; mi < 2; mi++) {
        #pragma unroll
        for (int rr = 0; rr < 2; rr++) {
            int r = wm * 32 + mi * 16 + rr * 8 + g;
            if (r < rows) {
                int tok  = tokS[r];
                float gt = gateS[r];
                float* orow = out + (size_t)tok * DM;
                #pragma unroll
                for (int ni = 0; ni < 8; ni++) {
                    int col = wn * 64 + ni * 8 + tg * 2;
                    float2 v;
                    v.x = (acc[mi][ni][rr * 2 + 0] + biasS[col])     * gt;
                    v.y = (acc[mi][ni][rr * 2 + 1] + biasS[col + 1]) * gt;
                    *reinterpret_cast<float2*>(orow + col) = v;
                }
            }
        }
    }
}

// ---------------- launch ---------------------------------------------------
extern "C" void kernel_launch(void* const* d_in, const int* in_sizes, int n_in,
                              void* d_out, int out_size)
{
    const float* x  = (const float*)d_in[0];
    const float* wg = (const float*)d_in[1];
    const float* W1 = (const float*)d_in[2];
    const float* b1 = (const float*)d_in[3];
    const float* W2 = (const float*)d_in[4];
    const float* b2 = (const float*)d_in[5];
    float* out = (float*)d_out;

    const int smem_bytes = (MT * XS_STRIDE + 2 * KB * WS_STRIDE + MT + DM + MT) * 4;
    cudaFuncSetAttribute(moe_gemm_kernel,
                         cudaFuncAttributeMaxDynamicSharedMemorySize, smem_bytes);

    zero_kernel<<<1, 32>>>();
    routing_kernel<<<256, 256>>>(x, wg);
    scan_kernel<<<1, 1>>>();
    perm_kernel<<<64, 1024>>>();
    moe_gemm_kernel<<<NE * TILES_PER_E, GEMM_THREADS, smem_bytes>>>(
        x, W1, b1, W2, b2, out);
}